// round 14
// baseline (speedup 1.0000x reference)
#include <cuda_runtime.h>
#include <cuda_bf16.h>
#include <cstdint>
#include <cstddef>

#define OBS_LEN 16
#define PRED_LEN 25
#define NNODES 192
#define PP (NNODES * NNODES)

// ---------------- device-global scratch ----------------
__device__ float g_Hngbr[PP * 64];          // 9.4 MB
__device__ float g_Hego[NNODES * 64];
__device__ float g_dyn[NNODES * 32];
__device__ float g_soc[NNODES * 144];
__device__ float g_WTd4[128 * 512];         // Whh_d packed [k/4][j][4]
__device__ float g_w1t[576 * 64];           // Wc1 transposed [c*9+u*3+v][o]
__device__ float g_w2t[576 * 16];

__device__ __forceinline__ float sigf(float x) { return __fdividef(1.f, 1.f + __expf(-x)); }
__device__ __forceinline__ float tanhx(float x) {
    float e = __expf(2.f * x);
    return 1.f - __fdividef(2.f, e + 1.f);
}
__device__ __forceinline__ float tanha(float x) {
    float y;
    asm("tanh.approx.f32 %0, %1;" : "=f"(y) : "f"(x));
    return y;
}
__device__ __forceinline__ float siga(float x) {   // sigmoid via tanh.approx
    return fmaf(tanha(0.5f * x), 0.5f, 0.5f);
}
__device__ __forceinline__ float lrelu(float x) { return x >= 0.f ? x : 0.1f * x; }

// pack two floats into bf16x2 (lo = first arg)
__device__ __forceinline__ uint32_t packbf(float lo, float hi) {
    __nv_bfloat162 p = __floats2bfloat162_rn(lo, hi);
    return *reinterpret_cast<uint32_t*>(&p);
}

// mma.sync m16n8k16 bf16 (sm_80 base feature)
__device__ __forceinline__ void mma16(float* d, const uint32_t* a, const uint32_t* b) {
    asm volatile(
        "mma.sync.aligned.m16n8k16.row.col.f32.bf16.bf16.f32 "
        "{%0,%1,%2,%3}, {%4,%5,%6,%7}, {%8,%9}, {%0,%1,%2,%3};"
        : "+f"(d[0]), "+f"(d[1]), "+f"(d[2]), "+f"(d[3])
        : "r"(a[0]), "r"(a[1]), "r"(a[2]), "r"(a[3]), "r"(b[0]), "r"(b[1]));
}

// ================= encoder LSTM via mma.sync bf16 (proven 312us build) =====
#define A_STRIDE_H 104
#define A_WORDS (64 * 52)
__global__ void __launch_bounds__(512, 1) enc_mma_kernel(
    const float* __restrict__ xng, const float* __restrict__ xego,
    const float* __restrict__ Wip, const float* __restrict__ bip,
    const float* __restrict__ Wih, const float* __restrict__ Whh,
    const float* __restrict__ bih, const float* __restrict__ bhh,
    float* __restrict__ Hng, float* __restrict__ Hego)
{
    __shared__ uint32_t As32[A_WORDS];      // bf16x2 pairs: [row][k/2]
    __shared__ float bsum[256];
    __shared__ float sWip[64], sbip[32];
    __nv_bfloat16* Ash = (__nv_bfloat16*)As32;

    const float* x; float* Hout; int tot, r0;
    if (blockIdx.x < 576) { x = xng;  Hout = Hng;  tot = PP;     r0 = blockIdx.x * 64; }
    else                  { x = xego; Hout = Hego; tot = NNODES; r0 = (blockIdx.x - 576) * 64; }

    const int tid = threadIdx.x, warp = tid >> 5, lane = tid & 31;
    const int gid = lane >> 2, tig = lane & 3;
    const int oddl = tig & 1;

    if (tid < 256) bsum[tid] = bih[tid] + bhh[tid];
    if (tid < 64) sWip[tid] = Wip[tid];
    if (tid < 32) sbip[tid] = bip[tid];
    for (int i = tid; i < A_WORDS; i += 512) As32[i] = 0u;

    // persistent B fragments (weights, bf16): 24 regs
    uint32_t breg[2][6][2];
#pragma unroll
    for (int j = 0; j < 2; ++j) {
        const int unit = 4 * warp + 2 * j + (gid >> 2);
        const int gate = gid & 3;
        const int z = gate * 64 + unit;
        const float* wih = Wih + z * 32;
        const float* whh = Whh + z * 64;
#pragma unroll
        for (int t = 0; t < 6; ++t) {
            const int kA = 16 * t + 2 * tig;
            const int kB = kA + 8;
            float a0 = (kA < 32) ? wih[kA] : whh[kA - 32];
            float a1 = (kA + 1 < 32) ? wih[kA + 1] : whh[kA - 31];
            float b0 = (kB < 32) ? wih[kB] : whh[kB - 32];
            float b1 = (kB + 1 < 32) ? wih[kB + 1] : whh[kB - 31];
            breg[j][t][0] = packbf(a0, a1);
            breg[j][t][1] = packbf(b0, b1);
        }
    }

    float cst[4][2];
#pragma unroll
    for (int i = 0; i < 4; ++i) { cst[i][0] = 0.f; cst[i][1] = 0.f; }

    const int urow_off = gid + (oddl ? 8 : 0);
    const int uoff = tig >> 1;
    const int erow = tid >> 3;
    const int ecb = (tid & 7) * 4;

    __syncthreads();
    float bload[2][2];
#pragma unroll
    for (int j = 0; j < 2; ++j) {
        const int cc0 = 2 * tig;
        const int unit_b = 4 * warp + 2 * j + (cc0 >> 2);
        bload[j][0] = bsum[(cc0 & 3) * 64 + unit_b];
        bload[j][1] = bsum[((cc0 + 1) & 3) * 64 + unit_b];
    }

    const float* xrow = x + (size_t)(r0 + erow) * 2;
    float px0 = xrow[0], px1 = xrow[1];

    for (int ts = 0; ts < OBS_LEN; ++ts) {
        {
            float v[4];
#pragma unroll
            for (int e = 0; e < 4; ++e) {
                int k = ecb + e;
                v[e] = lrelu(fmaf(sWip[k * 2], px0, fmaf(sWip[k * 2 + 1], px1, sbip[k])));
            }
            As32[erow * 52 + (ecb >> 1)] = packbf(v[0], v[1]);
            As32[erow * 52 + (ecb >> 1) + 1] = packbf(v[2], v[3]);
        }
        if (ts + 1 < OBS_LEN) {
            const float* nx = xrow + (size_t)(ts + 1) * tot * 2;
            px0 = nx[0]; px1 = nx[1];
        }
        __syncthreads();

        float acc[4][2][4];
#pragma unroll
        for (int j = 0; j < 2; ++j)
#pragma unroll
            for (int i = 0; i < 4; ++i) {
                acc[i][j][0] = bload[j][0]; acc[i][j][1] = bload[j][1];
                acc[i][j][2] = bload[j][0]; acc[i][j][3] = bload[j][1];
            }
#pragma unroll
        for (int t = 0; t < 6; ++t) {
            uint32_t a[4][4];
#pragma unroll
            for (int i = 0; i < 4; ++i) {
                const int r = 16 * i + gid;
                a[i][0] = As32[r * 52 + 8 * t + tig];
                a[i][1] = As32[(r + 8) * 52 + 8 * t + tig];
                a[i][2] = As32[r * 52 + 8 * t + 4 + tig];
                a[i][3] = As32[(r + 8) * 52 + 8 * t + 4 + tig];
            }
#pragma unroll
            for (int i = 0; i < 4; ++i)
#pragma unroll
                for (int j = 0; j < 2; ++j)
                    mma16(acc[i][j], a[i], breg[j][t]);
        }
        __syncthreads();

#pragma unroll
        for (int i = 0; i < 4; ++i) {
#pragma unroll
            for (int j = 0; j < 2; ++j) {
                float e0 = __shfl_xor_sync(0xffffffffu, acc[i][j][0], 1);
                float e1 = __shfl_xor_sync(0xffffffffu, acc[i][j][1], 1);
                float e2 = __shfl_xor_sync(0xffffffffu, acc[i][j][2], 1);
                float e3 = __shfl_xor_sync(0xffffffffu, acc[i][j][3], 1);
                float zi = oddl ? e2 : acc[i][j][0];
                float zf = oddl ? e3 : acc[i][j][1];
                float zg = oddl ? acc[i][j][2] : e0;
                float zo = oddl ? acc[i][j][3] : e1;
                float cs = siga(zf) * cst[i][j] + siga(zi) * tanha(zg);
                cst[i][j] = cs;
                float h = siga(zo) * tanha(cs);
                const int rowl = 16 * i + urow_off;
                const int ug = 4 * warp + 2 * j + uoff;
                Ash[rowl * A_STRIDE_H + 32 + ug] = __float2bfloat16(h);
                if (ts == OBS_LEN - 1)
                    Hout[(size_t)(r0 + rowl) * 64 + ug] = h;
            }
        }
    }
}

// ================= weight prep (one-time transposes) =================
__global__ void prep_kernel(const float* __restrict__ Wc1, const float* __restrict__ Wc2,
                            const float* __restrict__ Whh_d)
{
    int i = blockIdx.x * blockDim.x + threadIdx.x;
    if (i < 36864) { int o = i / 576, r = i - o * 576; g_w1t[r * 64 + o] = Wc1[i]; }
    if (i < 9216)  { int o = i / 576, r = i - o * 576; g_w2t[r * 16 + o] = Wc2[i]; }
    if (i < 512 * 128) {
        int j = i >> 7, k = i & 127;            // Whh_d[j][k]
        g_WTd4[(k >> 2) * 2048 + j * 4 + (k & 3)] = Whh_d[i];
    }
}

// ===== social (+fused dyn): gather + conv1 + conv2 + maxpool + traj_enc =====
__global__ void __launch_bounds__(384) social_kernel(
    const float* __restrict__ Hn, const float* __restrict__ He,
    const int* __restrict__ midx,
    const float* __restrict__ bc1, const float* __restrict__ bc2,
    const float* __restrict__ Wdyn, const float* __restrict__ bdyn,
    float* __restrict__ socout, float* __restrict__ dynout)
{
    __shared__ float in_s[64 * 65];
    __shared__ float wbuf[4608];
    __shared__ float mid[64 * 37];
    __shared__ float c2s[256];

    int tid = threadIdx.x, b = blockIdx.x;

    if (tid < 32) {
        float a = bdyn[tid];
        const float* h = He + b * 64;
        const float* w = Wdyn + tid * 64;
#pragma unroll 8
        for (int k = 0; k < 64; ++k) a = fmaf(w[k], h[k], a);
        dynout[b * 32 + tid] = lrelu(a);
    }

    for (int i = tid; i < 4096; i += 384) {
        int e = i & 63; int cell = i >> 6;
        int gh = cell >> 3, gw = cell & 7;
        int p = midx[b * 64 + cell];
        in_s[e * 65 + gw * 8 + gh] = Hn[p * 64 + e];
    }
    __syncthreads();

    int g = tid >> 6, o = tid & 63;
    float acc[6];
    float b1 = bc1[o];
#pragma unroll
    for (int q = 0; q < 6; ++q) acc[q] = b1;
    for (int c0 = 0; c0 < 64; c0 += 8) {
        __syncthreads();
        for (int i = tid; i < 4608; i += 384) wbuf[i] = g_w1t[c0 * 576 + i];
        __syncthreads();
#pragma unroll
        for (int cl = 0; cl < 8; ++cl) {
            int c = c0 + cl;
#pragma unroll
            for (int u = 0; u < 3; ++u) {
                float iv[8];
#pragma unroll
                for (int jj = 0; jj < 8; ++jj) iv[jj] = in_s[c * 65 + (g + u) * 8 + jj];
#pragma unroll
                for (int v = 0; v < 3; ++v) {
                    float w = wbuf[cl * 576 + (u * 3 + v) * 64 + o];
#pragma unroll
                    for (int q = 0; q < 6; ++q) acc[q] = fmaf(w, iv[q + v], acc[q]);
                }
            }
        }
    }
#pragma unroll
    for (int q = 0; q < 6; ++q) mid[o * 37 + g * 6 + q] = lrelu(acc[q]);
    __syncthreads();

    float acc2 = 0.f;
    int o2 = tid >> 4, pos = tid & 15, p2 = pos >> 2, q2 = pos & 3;
    if (tid < 256) acc2 = bc2[o2];
    for (int c0 = 0; c0 < 64; c0 += 8) {
        __syncthreads();
        for (int i = tid; i < 1152; i += 384) wbuf[i] = g_w2t[c0 * 144 + i];
        __syncthreads();
        if (tid < 256) {
#pragma unroll
            for (int cl = 0; cl < 8; ++cl) {
                int c = c0 + cl;
#pragma unroll
                for (int u = 0; u < 3; ++u)
#pragma unroll
                    for (int v = 0; v < 3; ++v)
                        acc2 = fmaf(mid[c * 37 + (p2 + u) * 6 + (q2 + v)],
                                    wbuf[cl * 144 + (u * 3 + v) * 16 + o2], acc2);
            }
        }
    }
    if (tid < 256) c2s[tid] = lrelu(acc2);
    __syncthreads();

    if (tid < 144) {
        int oo = tid / 9, pq = tid - oo * 9; int p = pq / 3, q = pq - p * 3;
        const float* base = c2s + oo * 16;
        float m = fmaxf(fmaxf(base[p * 4 + q], base[p * 4 + q + 1]),
                        fmaxf(base[(p + 1) * 4 + q], base[(p + 1) * 4 + q + 1]));
        socout[b * 144 + tid] = m;
    }
}

// ===== decoder: 192 blocks x 1 row, float4 weights, split accumulators =====
__global__ void __launch_bounds__(512) dec_kernel(
    const float* __restrict__ dyn, const float* __restrict__ soc,
    const float* __restrict__ Wih_d, const float* __restrict__ bih_d,
    const float* __restrict__ bhh_d,
    const float* __restrict__ Wop, const float* __restrict__ bop,
    float* __restrict__ out)
{
    __shared__ __align__(16) float h_s[128];
    __shared__ float z_s[512];
    __shared__ float ev[176];
    __shared__ float sWop[640];
    int tid = threadIdx.x, b = blockIdx.x;

    if (tid < 176)
        ev[tid] = (tid < 32) ? dyn[b * 32 + tid] : soc[b * 144 + tid - 32];
    for (int i = tid; i < 640; i += 512) sWop[i] = Wop[i];   // FIX: full coverage
    if (tid < 128) h_s[tid] = 0.f;
    __syncthreads();

    // fused z0
    float zin = bih_d[tid] + bhh_d[tid];
    {
        const float* w = Wih_d + tid * 176;
#pragma unroll 4
        for (int k = 0; k < 176; ++k) zin = fmaf(w[k], ev[k], zin);
    }
    float c = 0.f;
    const float4* WT4 = (const float4*)g_WTd4;
    const float4* H4 = (const float4*)h_s;

    for (int t = 0; t < PRED_LEN; ++t) {
        float a = zin, aa = 0.f;
#pragma unroll
        for (int q = 0; q < 32; ++q) {
            float4 w4 = WT4[q * 512 + tid];     // w(4q..4q+3, tid)
            float4 h4 = H4[q];                  // h[4q..4q+3], broadcast
            a  = fmaf(w4.x, h4.x, a);
            aa = fmaf(w4.y, h4.y, aa);
            a  = fmaf(w4.z, h4.z, a);
            aa = fmaf(w4.w, h4.w, aa);
        }
        z_s[tid] = a + aa;
        __syncthreads();
        if (tid < 128) {
            float zi = z_s[tid], zf = z_s[128 + tid];
            float zg = z_s[256 + tid], zo = z_s[384 + tid];
            c = sigf(zf) * c + sigf(zi) * tanhx(zg);
            h_s[tid] = sigf(zo) * tanhx(c);
        }
        __syncthreads();
        if (tid < 160) {  // 5 warps: output projection (Wop in smem)
            int oi = tid >> 5, ln = tid & 31;
            float a2 = 0.f;
#pragma unroll
            for (int k = ln; k < 128; k += 32) a2 = fmaf(sWop[oi * 128 + k], h_s[k], a2);
#pragma unroll
            for (int s = 16; s; s >>= 1) a2 += __shfl_down_sync(0xffffffffu, a2, s);
            if (ln == 0) {
                a2 += bop[oi];
                float v = (oi == 2 || oi == 3) ? __expf(a2) : (oi == 4 ? tanhx(a2) : a2);
                out[((size_t)t * NNODES + b) * 5 + oi] = v;
            }
        }
    }
}

// ================= launcher =================
extern "C" void kernel_launch(void* const* d_in, const int* in_sizes, int n_in,
                              void* d_out, int out_size)
{
    int wi = (n_in > 6 && in_sizes[6] == 1) ? 7 : 6;

    const float* obs_traj  = (const float*)d_in[0];
    const float* obs_ngbrs = (const float*)d_in[1];
    const int*   midx      = (const int*)d_in[3];
    const float* Wip   = (const float*)d_in[wi + 0];
    const float* bip   = (const float*)d_in[wi + 1];
    const float* Wih_e = (const float*)d_in[wi + 2];
    const float* Whh_e = (const float*)d_in[wi + 3];
    const float* bih_e = (const float*)d_in[wi + 4];
    const float* bhh_e = (const float*)d_in[wi + 5];
    const float* Wdyn  = (const float*)d_in[wi + 6];
    const float* bdyn  = (const float*)d_in[wi + 7];
    const float* Wc1   = (const float*)d_in[wi + 8];
    const float* bc1   = (const float*)d_in[wi + 9];
    const float* Wc2   = (const float*)d_in[wi + 10];
    const float* bc2   = (const float*)d_in[wi + 11];
    const float* Wih_d = (const float*)d_in[wi + 12];
    const float* Whh_d = (const float*)d_in[wi + 13];
    const float* bih_d = (const float*)d_in[wi + 14];
    const float* bhh_d = (const float*)d_in[wi + 15];
    const float* Wop   = (const float*)d_in[wi + 16];
    const float* bop   = (const float*)d_in[wi + 17];
    float* out = (float*)d_out;

    float *Hn, *He, *dynb, *socb;
    cudaGetSymbolAddress((void**)&Hn,   g_Hngbr);
    cudaGetSymbolAddress((void**)&He,   g_Hego);
    cudaGetSymbolAddress((void**)&dynb, g_dyn);
    cudaGetSymbolAddress((void**)&socb, g_soc);

    prep_kernel<<<256, 256>>>(Wc1, Wc2, Whh_d);
    enc_mma_kernel<<<579, 512>>>(obs_ngbrs, obs_traj, Wip, bip,
                                 Wih_e, Whh_e, bih_e, bhh_e, Hn, He);
    social_kernel<<<NNODES, 384>>>(Hn, He, midx, bc1, bc2, Wdyn, bdyn, socb, dynb);
    dec_kernel<<<NNODES, 512>>>(dynb, socb, Wih_d, bih_d, bhh_d, Wop, bop, out);
}

// round 15
// speedup vs baseline: 1.9142x; 1.9142x over previous
#include <cuda_runtime.h>
#include <cuda_bf16.h>
#include <cstdint>
#include <cstddef>

#define OBS_LEN 16
#define PRED_LEN 25
#define NNODES 192
#define PP (NNODES * NNODES)

// ---------------- device-global scratch ----------------
__device__ float g_Hngbr[PP * 64];          // 9.4 MB
__device__ float g_Hego[NNODES * 64];
__device__ float g_dyn[NNODES * 32];
__device__ float g_soc[NNODES * 144];
__device__ uint32_t g_Whh_bf[64 * 512];     // Whh_d bf16x2 packed [k/2][j]
__device__ float g_w1t[576 * 64];           // Wc1 transposed [c*9+u*3+v][o]
__device__ float g_w2t[576 * 16];

__device__ __forceinline__ float sigf(float x) { return __fdividef(1.f, 1.f + __expf(-x)); }
__device__ __forceinline__ float tanhx(float x) {
    float e = __expf(2.f * x);
    return 1.f - __fdividef(2.f, e + 1.f);
}
__device__ __forceinline__ float tanha(float x) {
    float y;
    asm("tanh.approx.f32 %0, %1;" : "=f"(y) : "f"(x));
    return y;
}
__device__ __forceinline__ float siga(float x) {   // sigmoid via tanh.approx
    return fmaf(tanha(0.5f * x), 0.5f, 0.5f);
}
__device__ __forceinline__ float lrelu(float x) { return x >= 0.f ? x : 0.1f * x; }

// pack two floats into bf16x2 (lo = first arg)
__device__ __forceinline__ uint32_t packbf(float lo, float hi) {
    __nv_bfloat162 p = __floats2bfloat162_rn(lo, hi);
    return *reinterpret_cast<uint32_t*>(&p);
}

// mma.sync m16n8k16 bf16 (sm_80 base feature)
__device__ __forceinline__ void mma16(float* d, const uint32_t* a, const uint32_t* b) {
    asm volatile(
        "mma.sync.aligned.m16n8k16.row.col.f32.bf16.bf16.f32 "
        "{%0,%1,%2,%3}, {%4,%5,%6,%7}, {%8,%9}, {%0,%1,%2,%3};"
        : "+f"(d[0]), "+f"(d[1]), "+f"(d[2]), "+f"(d[3])
        : "r"(a[0]), "r"(a[1]), "r"(a[2]), "r"(a[3]), "r"(b[0]), "r"(b[1]));
}

// ================= encoder LSTM via mma.sync bf16 (proven 312us build) =====
#define A_STRIDE_H 104
#define A_WORDS (64 * 52)
__global__ void __launch_bounds__(512, 1) enc_mma_kernel(
    const float* __restrict__ xng, const float* __restrict__ xego,
    const float* __restrict__ Wip, const float* __restrict__ bip,
    const float* __restrict__ Wih, const float* __restrict__ Whh,
    const float* __restrict__ bih, const float* __restrict__ bhh,
    float* __restrict__ Hng, float* __restrict__ Hego)
{
    __shared__ uint32_t As32[A_WORDS];      // bf16x2 pairs: [row][k/2]
    __shared__ float bsum[256];
    __shared__ float sWip[64], sbip[32];
    __nv_bfloat16* Ash = (__nv_bfloat16*)As32;

    const float* x; float* Hout; int tot, r0;
    if (blockIdx.x < 576) { x = xng;  Hout = Hng;  tot = PP;     r0 = blockIdx.x * 64; }
    else                  { x = xego; Hout = Hego; tot = NNODES; r0 = (blockIdx.x - 576) * 64; }

    const int tid = threadIdx.x, warp = tid >> 5, lane = tid & 31;
    const int gid = lane >> 2, tig = lane & 3;
    const int oddl = tig & 1;

    if (tid < 256) bsum[tid] = bih[tid] + bhh[tid];
    if (tid < 64) sWip[tid] = Wip[tid];
    if (tid < 32) sbip[tid] = bip[tid];
    for (int i = tid; i < A_WORDS; i += 512) As32[i] = 0u;

    // persistent B fragments (weights, bf16): 24 regs
    uint32_t breg[2][6][2];
#pragma unroll
    for (int j = 0; j < 2; ++j) {
        const int unit = 4 * warp + 2 * j + (gid >> 2);
        const int gate = gid & 3;
        const int z = gate * 64 + unit;
        const float* wih = Wih + z * 32;
        const float* whh = Whh + z * 64;
#pragma unroll
        for (int t = 0; t < 6; ++t) {
            const int kA = 16 * t + 2 * tig;
            const int kB = kA + 8;
            float a0 = (kA < 32) ? wih[kA] : whh[kA - 32];
            float a1 = (kA + 1 < 32) ? wih[kA + 1] : whh[kA - 31];
            float b0 = (kB < 32) ? wih[kB] : whh[kB - 32];
            float b1 = (kB + 1 < 32) ? wih[kB + 1] : whh[kB - 31];
            breg[j][t][0] = packbf(a0, a1);
            breg[j][t][1] = packbf(b0, b1);
        }
    }

    float cst[4][2];
#pragma unroll
    for (int i = 0; i < 4; ++i) { cst[i][0] = 0.f; cst[i][1] = 0.f; }

    const int urow_off = gid + (oddl ? 8 : 0);
    const int uoff = tig >> 1;
    const int erow = tid >> 3;
    const int ecb = (tid & 7) * 4;

    __syncthreads();
    float bload[2][2];
#pragma unroll
    for (int j = 0; j < 2; ++j) {
        const int cc0 = 2 * tig;
        const int unit_b = 4 * warp + 2 * j + (cc0 >> 2);
        bload[j][0] = bsum[(cc0 & 3) * 64 + unit_b];
        bload[j][1] = bsum[((cc0 + 1) & 3) * 64 + unit_b];
    }

    const float* xrow = x + (size_t)(r0 + erow) * 2;
    float px0 = xrow[0], px1 = xrow[1];

    for (int ts = 0; ts < OBS_LEN; ++ts) {
        {
            float v[4];
#pragma unroll
            for (int e = 0; e < 4; ++e) {
                int k = ecb + e;
                v[e] = lrelu(fmaf(sWip[k * 2], px0, fmaf(sWip[k * 2 + 1], px1, sbip[k])));
            }
            As32[erow * 52 + (ecb >> 1)] = packbf(v[0], v[1]);
            As32[erow * 52 + (ecb >> 1) + 1] = packbf(v[2], v[3]);
        }
        if (ts + 1 < OBS_LEN) {
            const float* nx = xrow + (size_t)(ts + 1) * tot * 2;
            px0 = nx[0]; px1 = nx[1];
        }
        __syncthreads();

        float acc[4][2][4];
#pragma unroll
        for (int j = 0; j < 2; ++j)
#pragma unroll
            for (int i = 0; i < 4; ++i) {
                acc[i][j][0] = bload[j][0]; acc[i][j][1] = bload[j][1];
                acc[i][j][2] = bload[j][0]; acc[i][j][3] = bload[j][1];
            }
#pragma unroll
        for (int t = 0; t < 6; ++t) {
            uint32_t a[4][4];
#pragma unroll
            for (int i = 0; i < 4; ++i) {
                const int r = 16 * i + gid;
                a[i][0] = As32[r * 52 + 8 * t + tig];
                a[i][1] = As32[(r + 8) * 52 + 8 * t + tig];
                a[i][2] = As32[r * 52 + 8 * t + 4 + tig];
                a[i][3] = As32[(r + 8) * 52 + 8 * t + 4 + tig];
            }
#pragma unroll
            for (int i = 0; i < 4; ++i)
#pragma unroll
                for (int j = 0; j < 2; ++j)
                    mma16(acc[i][j], a[i], breg[j][t]);
        }
        __syncthreads();

#pragma unroll
        for (int i = 0; i < 4; ++i) {
#pragma unroll
            for (int j = 0; j < 2; ++j) {
                float e0 = __shfl_xor_sync(0xffffffffu, acc[i][j][0], 1);
                float e1 = __shfl_xor_sync(0xffffffffu, acc[i][j][1], 1);
                float e2 = __shfl_xor_sync(0xffffffffu, acc[i][j][2], 1);
                float e3 = __shfl_xor_sync(0xffffffffu, acc[i][j][3], 1);
                float zi = oddl ? e2 : acc[i][j][0];
                float zf = oddl ? e3 : acc[i][j][1];
                float zg = oddl ? acc[i][j][2] : e0;
                float zo = oddl ? acc[i][j][3] : e1;
                float cs = siga(zf) * cst[i][j] + siga(zi) * tanha(zg);
                cst[i][j] = cs;
                float h = siga(zo) * tanha(cs);
                const int rowl = 16 * i + urow_off;
                const int ug = 4 * warp + 2 * j + uoff;
                Ash[rowl * A_STRIDE_H + 32 + ug] = __float2bfloat16(h);
                if (ts == OBS_LEN - 1)
                    Hout[(size_t)(r0 + rowl) * 64 + ug] = h;
            }
        }
    }
}

// ================= weight prep (one-time transposes + bf16 pack) ===========
__global__ void prep_kernel(const float* __restrict__ Wc1, const float* __restrict__ Wc2,
                            const float* __restrict__ Whh_d)
{
    int i = blockIdx.x * blockDim.x + threadIdx.x;
    if (i < 36864) { int o = i / 576, r = i - o * 576; g_w1t[r * 64 + o] = Wc1[i]; }
    if (i < 9216)  { int o = i / 576, r = i - o * 576; g_w2t[r * 16 + o] = Wc2[i]; }
    if (i < 64 * 512) {
        int kp = i >> 9, j = i & 511;           // Whh_d[j][k]
        g_Whh_bf[i] = packbf(Whh_d[j * 128 + 2 * kp], Whh_d[j * 128 + 2 * kp + 1]);
    }
}

// ===== social (+fused dyn): gather + conv1 + conv2 + maxpool + traj_enc =====
__global__ void __launch_bounds__(384) social_kernel(
    const float* __restrict__ Hn, const float* __restrict__ He,
    const int* __restrict__ midx,
    const float* __restrict__ bc1, const float* __restrict__ bc2,
    const float* __restrict__ Wdyn, const float* __restrict__ bdyn,
    float* __restrict__ socout, float* __restrict__ dynout)
{
    __shared__ float in_s[64 * 65];
    __shared__ float wbuf[4608];
    __shared__ float mid[64 * 37];
    __shared__ float c2s[256];

    int tid = threadIdx.x, b = blockIdx.x;

    if (tid < 32) {
        float a = bdyn[tid];
        const float* h = He + b * 64;
        const float* w = Wdyn + tid * 64;
#pragma unroll 8
        for (int k = 0; k < 64; ++k) a = fmaf(w[k], h[k], a);
        dynout[b * 32 + tid] = lrelu(a);
    }

    for (int i = tid; i < 4096; i += 384) {
        int e = i & 63; int cell = i >> 6;
        int gh = cell >> 3, gw = cell & 7;
        int p = midx[b * 64 + cell];
        in_s[e * 65 + gw * 8 + gh] = Hn[p * 64 + e];
    }
    __syncthreads();

    int g = tid >> 6, o = tid & 63;
    float acc[6];
    float b1 = bc1[o];
#pragma unroll
    for (int q = 0; q < 6; ++q) acc[q] = b1;
    for (int c0 = 0; c0 < 64; c0 += 8) {
        __syncthreads();
        for (int i = tid; i < 4608; i += 384) wbuf[i] = g_w1t[c0 * 576 + i];
        __syncthreads();
#pragma unroll
        for (int cl = 0; cl < 8; ++cl) {
            int c = c0 + cl;
#pragma unroll
            for (int u = 0; u < 3; ++u) {
                float iv[8];
#pragma unroll
                for (int jj = 0; jj < 8; ++jj) iv[jj] = in_s[c * 65 + (g + u) * 8 + jj];
#pragma unroll
                for (int v = 0; v < 3; ++v) {
                    float w = wbuf[cl * 576 + (u * 3 + v) * 64 + o];
#pragma unroll
                    for (int q = 0; q < 6; ++q) acc[q] = fmaf(w, iv[q + v], acc[q]);
                }
            }
        }
    }
#pragma unroll
    for (int q = 0; q < 6; ++q) mid[o * 37 + g * 6 + q] = lrelu(acc[q]);
    __syncthreads();

    float acc2 = 0.f;
    int o2 = tid >> 4, pos = tid & 15, p2 = pos >> 2, q2 = pos & 3;
    if (tid < 256) acc2 = bc2[o2];
    for (int c0 = 0; c0 < 64; c0 += 8) {
        __syncthreads();
        for (int i = tid; i < 1152; i += 384) wbuf[i] = g_w2t[c0 * 144 + i];
        __syncthreads();
        if (tid < 256) {
#pragma unroll
            for (int cl = 0; cl < 8; ++cl) {
                int c = c0 + cl;
#pragma unroll
                for (int u = 0; u < 3; ++u)
#pragma unroll
                    for (int v = 0; v < 3; ++v)
                        acc2 = fmaf(mid[c * 37 + (p2 + u) * 6 + (q2 + v)],
                                    wbuf[cl * 144 + (u * 3 + v) * 16 + o2], acc2);
            }
        }
    }
    if (tid < 256) c2s[tid] = lrelu(acc2);
    __syncthreads();

    if (tid < 144) {
        int oo = tid / 9, pq = tid - oo * 9; int p = pq / 3, q = pq - p * 3;
        const float* base = c2s + oo * 16;
        float m = fmaxf(fmaxf(base[p * 4 + q], base[p * 4 + q + 1]),
                        fmaxf(base[(p + 1) * 4 + q], base[(p + 1) * 4 + q + 1]));
        socout[b * 144 + tid] = m;
    }
}

// ===== decoder: 96 blocks x 2 rows, Whh in SMEM as bf16x2 (no L2 re-read) ===
__global__ void __launch_bounds__(512) dec_kernel(
    const float* __restrict__ dyn, const float* __restrict__ soc,
    const float* __restrict__ Wih_d, const float* __restrict__ bih_d,
    const float* __restrict__ bhh_d,
    const float* __restrict__ Wop, const float* __restrict__ bop,
    float* __restrict__ out)
{
    extern __shared__ uint32_t sW[];              // 32768 words = 128 KB
    __shared__ __align__(16) float hh[256];       // interleaved [k][row]
    __shared__ float z_s[2][512];
    __shared__ float ev[2][176];
    __shared__ float sWop[640];
    int tid = threadIdx.x, b = blockIdx.x, b2 = b * 2;

    for (int i = tid; i < 64 * 512; i += 512) sW[i] = g_Whh_bf[i];
    if (tid < 352) {
        int r = tid / 176, m = tid - r * 176;
        ev[r][m] = (m < 32) ? dyn[(b2 + r) * 32 + m] : soc[(b2 + r) * 144 + m - 32];
    }
    for (int i = tid; i < 640; i += 512) sWop[i] = Wop[i];
    if (tid < 256) hh[tid] = 0.f;
    __syncthreads();

    // fused z0: both rows share Wih_d row tid (fp32, exact)
    float zin0 = bih_d[tid] + bhh_d[tid];
    float zin1 = zin0;
    {
        const float* w = Wih_d + tid * 176;
#pragma unroll 4
        for (int k = 0; k < 176; ++k) {
            float wv = w[k];
            zin0 = fmaf(wv, ev[0][k], zin0);
            zin1 = fmaf(wv, ev[1][k], zin1);
        }
    }
    float c = 0.f;
    const float4* H4 = (const float4*)hh;
    const uint32_t* sWt = sW + tid;

    for (int t = 0; t < PRED_LEN; ++t) {
        float a0 = zin0, aa0 = 0.f, a1 = zin1, aa1 = 0.f;
#pragma unroll 16
        for (int kp = 0; kp < 64; ++kp) {
            uint32_t wu = sWt[kp * 512];
            float2 wf = __bfloat1622float2(*reinterpret_cast<const __nv_bfloat162*>(&wu));
            float4 h4 = H4[kp];        // h[2kp][r0..1], h[2kp+1][r0..1]
            a0  = fmaf(wf.x, h4.x, a0);
            a1  = fmaf(wf.x, h4.y, a1);
            aa0 = fmaf(wf.y, h4.z, aa0);
            aa1 = fmaf(wf.y, h4.w, aa1);
        }
        z_s[0][tid] = a0 + aa0; z_s[1][tid] = a1 + aa1;
        __syncthreads();
        if (tid < 256) {
            int r = tid >> 7, m = tid & 127;
            float zi = z_s[r][m], zf = z_s[r][128 + m];
            float zg = z_s[r][256 + m], zo = z_s[r][384 + m];
            c = sigf(zf) * c + sigf(zi) * tanhx(zg);
            hh[m * 2 + r] = sigf(zo) * tanhx(c);
        }
        __syncthreads();
        int wp = tid >> 5, ln = tid & 31;
        if (wp < 10) {  // 2 rows x 5 outputs
            int r = wp / 5, oi = wp - r * 5;
            float a2 = 0.f;
#pragma unroll
            for (int k = ln; k < 128; k += 32) a2 = fmaf(sWop[oi * 128 + k], hh[k * 2 + r], a2);
#pragma unroll
            for (int s = 16; s; s >>= 1) a2 += __shfl_down_sync(0xffffffffu, a2, s);
            if (ln == 0) {
                a2 += bop[oi];
                float v = (oi == 2 || oi == 3) ? __expf(a2) : (oi == 4 ? tanhx(a2) : a2);
                out[((size_t)t * NNODES + b2 + r) * 5 + oi] = v;
            }
        }
    }
}

// ================= launcher =================
extern "C" void kernel_launch(void* const* d_in, const int* in_sizes, int n_in,
                              void* d_out, int out_size)
{
    int wi = (n_in > 6 && in_sizes[6] == 1) ? 7 : 6;

    const float* obs_traj  = (const float*)d_in[0];
    const float* obs_ngbrs = (const float*)d_in[1];
    const int*   midx      = (const int*)d_in[3];
    const float* Wip   = (const float*)d_in[wi + 0];
    const float* bip   = (const float*)d_in[wi + 1];
    const float* Wih_e = (const float*)d_in[wi + 2];
    const float* Whh_e = (const float*)d_in[wi + 3];
    const float* bih_e = (const float*)d_in[wi + 4];
    const float* bhh_e = (const float*)d_in[wi + 5];
    const float* Wdyn  = (const float*)d_in[wi + 6];
    const float* bdyn  = (const float*)d_in[wi + 7];
    const float* Wc1   = (const float*)d_in[wi + 8];
    const float* bc1   = (const float*)d_in[wi + 9];
    const float* Wc2   = (const float*)d_in[wi + 10];
    const float* bc2   = (const float*)d_in[wi + 11];
    const float* Wih_d = (const float*)d_in[wi + 12];
    const float* Whh_d = (const float*)d_in[wi + 13];
    const float* bih_d = (const float*)d_in[wi + 14];
    const float* bhh_d = (const float*)d_in[wi + 15];
    const float* Wop   = (const float*)d_in[wi + 16];
    const float* bop   = (const float*)d_in[wi + 17];
    float* out = (float*)d_out;

    float *Hn, *He, *dynb, *socb;
    cudaGetSymbolAddress((void**)&Hn,   g_Hngbr);
    cudaGetSymbolAddress((void**)&He,   g_Hego);
    cudaGetSymbolAddress((void**)&dynb, g_dyn);
    cudaGetSymbolAddress((void**)&socb, g_soc);

    const int dec_smem = 64 * 512 * 4;   // 131072 B
    cudaFuncSetAttribute(dec_kernel, cudaFuncAttributeMaxDynamicSharedMemorySize, dec_smem);

    prep_kernel<<<256, 256>>>(Wc1, Wc2, Whh_d);
    enc_mma_kernel<<<579, 512>>>(obs_ngbrs, obs_traj, Wip, bip,
                                 Wih_e, Whh_e, bih_e, bhh_e, Hn, He);
    social_kernel<<<NNODES, 384>>>(Hn, He, midx, bc1, bc2, Wdyn, bdyn, socb, dynb);
    dec_kernel<<<NNODES / 2, 512, dec_smem>>>(dynb, socb, Wih_d, bih_d, bhh_d, Wop, bop, out);
}